// round 17
// baseline (speedup 1.0000x reference)
#include <cuda_runtime.h>
#include <cuda_fp16.h>
#include <cuda_bf16.h>
#include <cstdint>
#include <math.h>

#define BB 4
#define NN 4096
#define DD 256
#define KTOP 64
#define EPSN 1e-12f

#define PACKW 256             // fp16 row
#define NCHUNK 4              // K=256 in 64-element chunks
#define STAGE 32768           // 16KB A + 16KB B per stage

// ---------------- scratch ----------------
__device__ __nv_bfloat16  g_value[(size_t)BB * NN * DD];
__device__ __half         g_cos  [(size_t)BB * NN * NN];        // fp16 cos (128 MB)
__device__ __half         g_pack [(size_t)BB * NN * PACKW];
__device__ __half         g_Wpack[(size_t)DD * PACKW];
__device__ float          g_norm [(size_t)BB * NN];
__device__ float          g_xsum_part[BB * 16 * DD];
__device__ float          g_sumv[BB * DD];

__device__ __forceinline__ uint32_t smem_to_u32(const void* p) {
    uint32_t a;
    asm("{ .reg .u64 t; cvta.to.shared.u64 t, %1; cvt.u32.u64 %0, t; }" : "=r"(a) : "l"(p));
    return a;
}
__device__ __forceinline__ void ldsm4(uint32_t& r0, uint32_t& r1, uint32_t& r2, uint32_t& r3, uint32_t addr) {
    asm volatile("ldmatrix.sync.aligned.m8n8.x4.shared.b16 {%0,%1,%2,%3}, [%4];"
        : "=r"(r0), "=r"(r1), "=r"(r2), "=r"(r3) : "r"(addr));
}
__device__ __forceinline__ void mma16816(float* d, const uint32_t* a, const uint32_t* b) {
    asm volatile("mma.sync.aligned.m16n8k16.row.col.f32.f16.f16.f32 "
        "{%0,%1,%2,%3}, {%4,%5,%6,%7}, {%8,%9}, {%0,%1,%2,%3};"
        : "+f"(d[0]), "+f"(d[1]), "+f"(d[2]), "+f"(d[3])
        : "r"(a[0]), "r"(a[1]), "r"(a[2]), "r"(a[3]), "r"(b[0]), "r"(b[1]));
}
__device__ __forceinline__ void cp_async16(uint32_t saddr, const void* gptr) {
    asm volatile("cp.async.cg.shared.global [%0], [%1], 16;" :: "r"(saddr), "l"(gptr) : "memory");
}
#define CP_COMMIT() asm volatile("cp.async.commit_group;" ::: "memory")
#define CP_WAIT(N)  asm volatile("cp.async.wait_group %0;" :: "n"(N) : "memory")

// order-preserving 16-bit key for fp16 bits
__device__ __forceinline__ unsigned key16(unsigned h) {
    return (h & 0x8000u) ? ((~h) & 0xFFFFu) : (h | 0x8000u);
}
__device__ __forceinline__ float val_of_key16(unsigned k) {
    unsigned h = (k & 0x8000u) ? (k & 0x7FFFu) : ((~k) & 0xFFFFu);
    __half hv = __ushort_as_half((unsigned short)h);
    return __half2float(hv);
}

// ---------------- 1) normalize + fp16 pack + norm save (+ W pack piggyback) ----------------
__global__ void __launch_bounds__(DD) normalize_pack_kernel(const float* __restrict__ x,
                                                            const float* __restrict__ W)
{
    int row = blockIdx.x;
    int d   = threadIdx.x;
    float v = x[(size_t)row * DD + d];
    float s = v * v;
    __shared__ float red[8];
    #pragma unroll
    for (int o = 16; o; o >>= 1) s += __shfl_xor_sync(0xffffffffu, s, o);
    if ((d & 31) == 0) red[d >> 5] = s;
    __syncthreads();
    if (d < 32) {
        float t = (d < 8) ? red[d] : 0.f;
        #pragma unroll
        for (int o = 4; o; o >>= 1) t += __shfl_xor_sync(0xffffffffu, t, o);
        if (d == 0) red[0] = t;
    }
    __syncthreads();
    float norm = sqrtf(red[0]);
    float nv = v / fmaxf(norm, EPSN);

    g_pack[(size_t)row * PACKW + d] = __float2half(nv);
    if (d == 0) g_norm[row] = norm;

    if (row < DD)
        g_Wpack[(size_t)row * PACKW + d] = __float2half(W[(size_t)row * DD + d]);
}

// ---------------- 1b) per-batch partial column sums of x ----------------
__global__ void __launch_bounds__(DD) xsum_part_kernel(const float* __restrict__ x)
{
    int b = blockIdx.y, c = blockIdx.x, e = threadIdx.x;
    const float* base = x + (size_t)b * NN * DD + (size_t)c * 256 * DD + e;
    float s = 0.f;
    #pragma unroll 8
    for (int n = 0; n < 256; n++) s += base[(size_t)n * DD];
    g_xsum_part[(b * 16 + c) * DD + e] = s;
}

// ---------------- 1c) sumv = (colsum x) @ W^T + N*b  (exact algebra) ----------------
__global__ void __launch_bounds__(DD) sumv_mv_kernel(const float* __restrict__ W,
                                                     const float* __restrict__ bias)
{
    int b = blockIdx.x, t = threadIdx.x;
    __shared__ float xs[DD];
    float s = 0.f;
    #pragma unroll
    for (int c = 0; c < 16; c++) s += g_xsum_part[(b * 16 + c) * DD + t];
    xs[t] = s;
    __syncthreads();
    float acc = 0.f;
    const float4* Wr = (const float4*)&W[(size_t)t * DD];
    #pragma unroll 8
    for (int d4 = 0; d4 < 64; d4++) {
        float4 w = Wr[d4];
        acc += xs[d4 * 4 + 0] * w.x + xs[d4 * 4 + 1] * w.y
             + xs[d4 * 4 + 2] * w.z + xs[d4 * 4 + 3] * w.w;
    }
    g_sumv[b * DD + t] = acc + (float)NN * bias[t];
}

// ---------------- 2) value = norm * (nx @ W^T) + b  -> bf16  (fp16 mma, 2-stage, 3 CTA/SM) ----------------
__global__ void __launch_bounds__(256, 3) valuemma_kernel(const float* __restrict__ bias)
{
    extern __shared__ char smem[];
    const uint32_t sb = smem_to_u32(smem);

    const int tid  = threadIdx.x;
    const int wid  = tid >> 5;
    const int lane = tid & 31;
    const int wm   = wid & 3;
    const int wn   = wid >> 2;
    const int m0   = blockIdx.y * 128;
    const int n0   = blockIdx.x * 128;

    const __half* Agl = g_pack  + (size_t)m0 * PACKW;
    const __half* Bgl = g_Wpack + (size_t)n0 * PACKW;

    const int lr = tid >> 3;
    const int lj = tid & 7;

    auto load_chunk_async = [&](int c, int s) {
        const char* ga = (const char*)Agl + (size_t)c * 128;
        const char* gb = (const char*)Bgl + (size_t)c * 128;
        uint32_t sa = sb + s * STAGE;
        uint32_t sbm = sa + 16384;
        #pragma unroll
        for (int k = 0; k < 4; k++) {
            int r = lr + 32 * k;
            uint32_t off = r * 128 + ((lj ^ (r & 7)) << 4);
            cp_async16(sa + off,  ga + (size_t)r * (PACKW * 2) + lj * 16);
            cp_async16(sbm + off, gb + (size_t)r * (PACKW * 2) + lj * 16);
        }
    };

    float acc[2][8][4];
    #pragma unroll
    for (int ia = 0; ia < 2; ia++)
        #pragma unroll
        for (int j = 0; j < 8; j++)
            #pragma unroll
            for (int q = 0; q < 4; q++) acc[ia][j][q] = 0.f;

    const int arow_lo = (lane & 7) + ((lane >> 3) & 1) * 8;
    const int a_cc_add = (lane >> 4);
    const int brow_lo = (lane & 7) + ((lane >> 4) ? 8 : 0);
    const int b_cc_add = ((lane >> 3) & 1);

    load_chunk_async(0, 0); CP_COMMIT();

    for (int c = 0; c < NCHUNK; c++) {
        int s = c & 1;
        if (c + 1 < NCHUNK) { load_chunk_async(c + 1, s ^ 1); CP_COMMIT(); CP_WAIT(1); }
        else                { CP_WAIT(0); }
        __syncthreads();

        const uint32_t abase = sb + s * STAGE;
        const uint32_t bbase = abase + 16384;

        #pragma unroll
        for (int ks = 0; ks < 4; ks++) {
            uint32_t af[2][4], bf[8][2];
            #pragma unroll
            for (int ia = 0; ia < 2; ia++) {
                int row = wm * 32 + ia * 16 + arow_lo;
                uint32_t cc = 2 * ks + a_cc_add;
                uint32_t addr = abase + row * 128 + ((cc << 4) ^ ((row & 7) << 4));
                ldsm4(af[ia][0], af[ia][1], af[ia][2], af[ia][3], addr);
            }
            #pragma unroll
            for (int L = 0; L < 4; L++) {
                int row = wn * 64 + L * 16 + brow_lo;
                uint32_t cc = 2 * ks + b_cc_add;
                uint32_t addr = bbase + row * 128 + ((cc << 4) ^ ((row & 7) << 4));
                ldsm4(bf[2 * L][0], bf[2 * L][1], bf[2 * L + 1][0], bf[2 * L + 1][1], addr);
            }
            #pragma unroll
            for (int ia = 0; ia < 2; ia++)
                #pragma unroll
                for (int j = 0; j < 8; j++)
                    mma16816(acc[ia][j], af[ia], bf[j]);
        }
        __syncthreads();
    }

    const int g = lane >> 2, q = lane & 3;
    #pragma unroll
    for (int ia = 0; ia < 2; ia++) {
        int row = m0 + wm * 32 + ia * 16 + g;
        float nr0 = __ldg(&g_norm[row]);
        float nr8 = __ldg(&g_norm[row + 8]);
        #pragma unroll
        for (int j = 0; j < 8; j++) {
            int col = n0 + wn * 64 + j * 8 + q * 2;
            float b0 = __ldg(&bias[col]), b1 = __ldg(&bias[col + 1]);
            __nv_bfloat162 v01 = __floats2bfloat162_rn(acc[ia][j][0] * nr0 + b0, acc[ia][j][1] * nr0 + b1);
            __nv_bfloat162 v23 = __floats2bfloat162_rn(acc[ia][j][2] * nr8 + b0, acc[ia][j][3] * nr8 + b1);
            *(__nv_bfloat162*)&g_value[(size_t)row * DD + col]       = v01;
            *(__nv_bfloat162*)&g_value[(size_t)(row + 8) * DD + col] = v23;
        }
    }
}

// ---------------- 4) cos = nx @ nx^T  (fp16 mma, fp16 out, 2-stage, 3 CTA/SM) ----------------
__global__ void __launch_bounds__(256, 3) cosmma_kernel(__half* __restrict__ C, int b)
{
    extern __shared__ char smem[];
    const uint32_t sb = smem_to_u32(smem);

    const int tid  = threadIdx.x;
    const int wid  = tid >> 5;
    const int lane = tid & 31;
    const int wm   = wid & 3;
    const int wn   = wid >> 2;

    int i  = blockIdx.x;
    int by = (int)((sqrtf(8.f * (float)i + 1.f) - 1.f) * 0.5f);
    while ((by + 1) * (by + 2) / 2 <= i) by++;
    while (by * (by + 1) / 2 > i) by--;
    int bx = i - by * (by + 1) / 2;
    const int m0 = by * 128;
    const int n0 = bx * 128;

    const __half* Agl = g_pack + ((size_t)b * NN + m0) * PACKW;
    const __half* Bgl = g_pack + ((size_t)b * NN + n0) * PACKW;

    const int lr = tid >> 3;
    const int lj = tid & 7;

    auto load_chunk_async = [&](int c, int s) {
        const char* ga = (const char*)Agl + (size_t)c * 128;
        const char* gb = (const char*)Bgl + (size_t)c * 128;
        uint32_t sa = sb + s * STAGE;
        uint32_t sbm = sa + 16384;
        #pragma unroll
        for (int k = 0; k < 4; k++) {
            int r = lr + 32 * k;
            uint32_t off = r * 128 + ((lj ^ (r & 7)) << 4);
            cp_async16(sa + off,  ga + (size_t)r * (PACKW * 2) + lj * 16);
            cp_async16(sbm + off, gb + (size_t)r * (PACKW * 2) + lj * 16);
        }
    };

    float acc[2][8][4];
    #pragma unroll
    for (int ia = 0; ia < 2; ia++)
        #pragma unroll
        for (int j = 0; j < 8; j++)
            #pragma unroll
            for (int q = 0; q < 4; q++) acc[ia][j][q] = 0.f;

    const int arow_lo = (lane & 7) + ((lane >> 3) & 1) * 8;
    const int a_cc_add = (lane >> 4);
    const int brow_lo = (lane & 7) + ((lane >> 4) ? 8 : 0);
    const int b_cc_add = ((lane >> 3) & 1);

    load_chunk_async(0, 0); CP_COMMIT();

    for (int c = 0; c < NCHUNK; c++) {
        int s = c & 1;
        if (c + 1 < NCHUNK) { load_chunk_async(c + 1, s ^ 1); CP_COMMIT(); CP_WAIT(1); }
        else                { CP_WAIT(0); }
        __syncthreads();

        const uint32_t abase = sb + s * STAGE;
        const uint32_t bbase = abase + 16384;

        #pragma unroll
        for (int ks = 0; ks < 4; ks++) {
            uint32_t af[2][4], bf[8][2];
            #pragma unroll
            for (int ia = 0; ia < 2; ia++) {
                int row = wm * 32 + ia * 16 + arow_lo;
                uint32_t cc = 2 * ks + a_cc_add;
                uint32_t addr = abase + row * 128 + ((cc << 4) ^ ((row & 7) << 4));
                ldsm4(af[ia][0], af[ia][1], af[ia][2], af[ia][3], addr);
            }
            #pragma unroll
            for (int L = 0; L < 4; L++) {
                int row = wn * 64 + L * 16 + brow_lo;
                uint32_t cc = 2 * ks + b_cc_add;
                uint32_t addr = bbase + row * 128 + ((cc << 4) ^ ((row & 7) << 4));
                ldsm4(bf[2 * L][0], bf[2 * L][1], bf[2 * L + 1][0], bf[2 * L + 1][1], addr);
            }
            #pragma unroll
            for (int ia = 0; ia < 2; ia++)
                #pragma unroll
                for (int j = 0; j < 8; j++)
                    mma16816(acc[ia][j], af[ia], bf[j]);
        }
        __syncthreads();
    }

    __half* Cb = C + (size_t)b * NN * NN;
    const int g = lane >> 2, q = lane & 3;
    #pragma unroll
    for (int ia = 0; ia < 2; ia++) {
        int row = m0 + wm * 32 + ia * 16 + g;
        #pragma unroll
        for (int j = 0; j < 8; j++) {
            int col = n0 + wn * 64 + j * 8 + q * 2;
            __half2 h01 = __floats2half2_rn(acc[ia][j][0], acc[ia][j][1]);
            __half2 h23 = __floats2half2_rn(acc[ia][j][2], acc[ia][j][3]);
            *(__half2*)&Cb[(size_t)row * NN + col]       = h01;
            *(__half2*)&Cb[(size_t)(row + 8) * NN + col] = h23;
            if (bx != by) {
                Cb[(size_t)col * NN + row]           = __low2half(h01);
                Cb[(size_t)(col + 1) * NN + row]     = __high2half(h01);
                Cb[(size_t)col * NN + row + 8]       = __low2half(h23);
                Cb[(size_t)(col + 1) * NN + row + 8] = __high2half(h23);
            }
        }
    }
}

// ---------------- 5) 1-pass 2048-bin select top-64 + fused output; per batch ----------------
__global__ void __launch_bounds__(256) topk_out_kernel(float* __restrict__ out, int b)
{
    const int n = blockIdx.x;
    const int t = threadIdx.x;
    const int lane = t & 31;
    const int wid = t >> 5;

    __shared__ int      hist[2048];      // 11-bit bins of key16
    __shared__ int      wtot[8];
    __shared__ int      sh_tbin;
    __shared__ float    red_f[8];
    __shared__ int      sel_idx[KTOP];
    __shared__ unsigned sel_key[KTOP];
    __shared__ float    sel_w[KTOP];
    __shared__ int      bd_idx[256];
    __shared__ unsigned bd_key[256];
    __shared__ int      cnt_gt, cnt_bd;
    __shared__ float    Zsh;

    const __half* row = g_cos + ((size_t)b * NN + n) * NN;

    uint32_t kk[8];
    *(uint4*)&kk[0] = ((const uint4*)row)[2 * t];
    *(uint4*)&kk[4] = ((const uint4*)row)[2 * t + 1];
    unsigned kreg[16];
    #pragma unroll
    for (int j = 0; j < 16; j++)
        kreg[j] = key16((kk[j >> 1] >> ((j & 1) * 16)) & 0xFFFFu);

    if (t == 0) { cnt_gt = 0; cnt_bd = 0; }
    #pragma unroll
    for (int i = 0; i < 8; i++) hist[t * 8 + i] = 0;
    __syncthreads();

    // single counting pass (11-bit bins)
    #pragma unroll
    for (int j = 0; j < 16; j++) atomicAdd(&hist[kreg[j] >> 5], 1);
    __syncthreads();

    // descending block scan to find threshold bin
    int loc[8], lsum = 0;
    #pragma unroll
    for (int i = 0; i < 8; i++) { loc[i] = hist[2047 - 8 * t - i]; lsum += loc[i]; }
    int incl = lsum;
    #pragma unroll
    for (int o = 1; o < 32; o <<= 1) {
        int v = __shfl_up_sync(0xffffffffu, incl, o);
        if (lane >= o) incl += v;
    }
    if (lane == 31) wtot[wid] = incl;
    __syncthreads();
    int wbase = 0;
    #pragma unroll
    for (int w = 0; w < 8; w++) if (w < wid) wbase += wtot[w];
    int excl = wbase + incl - lsum;
    if (excl < KTOP && KTOP <= excl + lsum) {
        int run = excl;
        #pragma unroll
        for (int i = 0; i < 8; i++) {
            if (run + loc[i] >= KTOP) { sh_tbin = 2047 - 8 * t - i; break; }
            run += loc[i];
        }
    }
    __syncthreads();
    const int Tbin = sh_tbin;

    // selection: definite (bin > Tbin) + boundary candidates (bin == Tbin)
    #pragma unroll
    for (int j = 0; j < 16; j++) {
        unsigned u = kreg[j];
        int bin = (int)(u >> 5);
        int idx = 16 * t + j;
        if (bin > Tbin) {
            int p = atomicAdd(&cnt_gt, 1);
            sel_idx[p] = idx;
            sel_key[p] = u;
        } else if (bin == Tbin) {
            int p = atomicAdd(&cnt_bd, 1);
            if (p < 256) { bd_idx[p] = idx; bd_key[p] = u; }
        }
    }
    __syncthreads();

    const int ngt = cnt_gt;
    const int krem = KTOP - ngt;
    if (t == 0) {
        int nb = cnt_bd < 256 ? cnt_bd : 256;
        // insertion sort by (key desc, idx asc) — typical nb ~ 10
        for (int a = 1; a < nb; a++) {
            unsigned kv = bd_key[a]; int iv = bd_idx[a];
            int c2 = a - 1;
            while (c2 >= 0 && (bd_key[c2] < kv || (bd_key[c2] == kv && bd_idx[c2] > iv))) {
                bd_key[c2 + 1] = bd_key[c2]; bd_idx[c2 + 1] = bd_idx[c2]; c2--;
            }
            bd_key[c2 + 1] = kv; bd_idx[c2 + 1] = iv;
        }
        for (int a = 0; a < krem; a++) {
            sel_idx[ngt + a] = bd_idx[a];
            sel_key[ngt + a] = bd_key[a];
        }
    }
    __syncthreads();

    float e_val = 0.f;
    if (t < KTOP) {
        e_val = expf(val_of_key16(sel_key[t]));
        sel_w[t] = e_val - 1.0f;
    }
    float s = e_val;
    #pragma unroll
    for (int o = 16; o; o >>= 1) s += __shfl_xor_sync(0xffffffffu, s, o);
    if ((t & 31) == 0) red_f[t >> 5] = s;
    __syncthreads();
    if (t == 0) {
        float z = (float)(NN - KTOP);
        #pragma unroll
        for (int w = 0; w < 8; w++) z += red_f[w];
        Zsh = z;
    }
    __syncthreads();

    const __nv_bfloat16* Vb = g_value + (size_t)b * NN * DD;
    float acc = g_sumv[b * DD + t];
    const float invZ = 1.0f / Zsh;
    #pragma unroll 8
    for (int k = 0; k < KTOP; k++)
        acc += sel_w[k] * __bfloat162float(Vb[(size_t)sel_idx[k] * DD + t]);
    out[((size_t)b * NN + n) * DD + t] = acc * invZ;
}

// ---------------- launch: two-stream per-batch pipeline ----------------
extern "C" void kernel_launch(void* const* d_in, const int* in_sizes, int n_in,
                              void* d_out, int out_size)
{
    const float* x    = (const float*)d_in[0];
    const float* W    = (const float*)d_in[1];
    const float* bias = (const float*)d_in[2];
    float*       out  = (float*)d_out;

    __half* p_cos;
    cudaGetSymbolAddress((void**)&p_cos, g_cos);

    static bool init_done = false;
    static cudaStream_t s1;
    static cudaEvent_t ev_pack, ev_cos[BB], ev_join;
    if (!init_done) {
        cudaStreamCreateWithFlags(&s1, cudaStreamNonBlocking);
        cudaEventCreateWithFlags(&ev_pack, cudaEventDisableTiming);
        for (int b = 0; b < BB; b++) cudaEventCreateWithFlags(&ev_cos[b], cudaEventDisableTiming);
        cudaEventCreateWithFlags(&ev_join, cudaEventDisableTiming);

        const int SM = 2 * STAGE;
        cudaFuncSetAttribute(cosmma_kernel,   cudaFuncAttributeMaxDynamicSharedMemorySize, SM);
        cudaFuncSetAttribute(valuemma_kernel, cudaFuncAttributeMaxDynamicSharedMemorySize, SM);
        init_done = true;
    }
    const int MMA_SMEM = 2 * STAGE;     // 65536
    const int COS_GRID = (NN / 128) * (NN / 128 + 1) / 2;   // 528

    // s0: pack, then cos per batch
    normalize_pack_kernel<<<BB * NN, DD>>>(x, W);
    cudaEventRecord(ev_pack, 0);
    for (int b = 0; b < BB; b++) {
        cosmma_kernel<<<COS_GRID, 256, MMA_SMEM>>>(p_cos, b);
        cudaEventRecord(ev_cos[b], 0);
    }

    // s1: topk prologue, then topk per batch gated on cos events
    xsum_part_kernel<<<dim3(16, BB), DD, 0, s1>>>(x);
    cudaStreamWaitEvent(s1, ev_pack, 0);
    valuemma_kernel<<<dim3(DD / 128, (BB * NN) / 128), 256, MMA_SMEM, s1>>>(bias);
    sumv_mv_kernel<<<BB, DD, 0, s1>>>(W, bias);
    for (int b = 0; b < BB; b++) {
        cudaStreamWaitEvent(s1, ev_cos[b], 0);
        topk_out_kernel<<<NN, 256, 0, s1>>>(out, b);
    }

    cudaEventRecord(ev_join, s1);
    cudaStreamWaitEvent(0, ev_join, 0);
}